// round 11
// baseline (speedup 1.0000x reference)
#include <cuda_runtime.h>
#include <cuda_fp16.h>
#include <math.h>
#include <stdint.h>

#define E_TOTAL 65536     // B*N*K
#define W3OFF   768       // SPLIT_OFF
#define RPN     768       // SPLIT_SZ

// ---- device scratch ----
__device__ __half g_W1h[256 * 32],  g_W1l[256 * 32];
__device__ __half g_W2h[256 * 256];
__device__ __half g_W3h[768 * 256];
__device__ __half g_H1[(size_t)E_TOTAL * 256];
__device__ __half g_H2[(size_t)E_TOTAL * 256];
__device__ float  g_TMP[(size_t)E_TOTAL * 144];   // tmp[e][dd][j], 37.7 MB

__device__ __forceinline__ float gelu_exact(float x) {
    return 0.5f * x * (1.0f + erff(x * 0.70710678118654752440f));
}

// ---------------------------------------------------------------------------
#define CPA16(dst_u32, src_ptr) \
    asm volatile("cp.async.cg.shared.global [%0], [%1], 16;" :: "r"(dst_u32), "l"(src_ptr))
#define CPA_COMMIT() asm volatile("cp.async.commit_group;" ::: "memory")
#define CPA_WAIT(n)  asm volatile("cp.async.wait_group %0;" :: "n"(n) : "memory")

#define LDSM4(R, addr)                                                        \
    asm volatile("ldmatrix.sync.aligned.m8n8.x4.shared.b16 {%0,%1,%2,%3}, [%4];" \
                 : "=r"((R)[0]), "=r"((R)[1]), "=r"((R)[2]), "=r"((R)[3])     \
                 : "r"(addr))

__device__ __forceinline__ void mma_f16(float* d, const uint32_t* a,
                                        uint32_t b0, uint32_t b1) {
    asm volatile(
        "mma.sync.aligned.m16n8k16.row.col.f32.f16.f16.f32 "
        "{%0,%1,%2,%3}, {%4,%5,%6,%7}, {%8,%9}, {%0,%1,%2,%3};"
        : "+f"(d[0]), "+f"(d[1]), "+f"(d[2]), "+f"(d[3])
        : "r"(a[0]), "r"(a[1]), "r"(a[2]), "r"(a[3]), "r"(b0), "r"(b1));
}

// swizzled byte offset for 64B rows (4 chunks of 16B); conflict-free for
// cp.async stores AND ldmatrix phases (validated R4/R6-R9).
__device__ __forceinline__ uint32_t soff(int r, int c) {
    return (uint32_t)((r * 4 + (c ^ ((r >> 1) & 3))) << 4);
}

// ---------------------------------------------------------------------------
__global__ void prep_weight(const float* __restrict__ W, int K, int N, int ldw,
                            int coff, __half* __restrict__ hi, __half* __restrict__ lo)
{
    int idx = blockIdx.x * 256 + threadIdx.x;
    if (idx >= N * K) return;
    int n = idx / K, k = idx - n * K;
    float v = W[(size_t)k * ldw + coff + n];
    __half h = __float2half_rn(v);
    hi[idx] = h;
    if (lo) lo[idx] = __float2half_rn(v - __half2float(h));
}

// zero the output buffer (re-zeroed every graph replay before atomics)
__global__ void zero_out(float4* __restrict__ out)
{
    out[blockIdx.x * 256 + threadIdx.x] = make_float4(0.f, 0.f, 0.f, 0.f);
}

// ---------------------------------------------------------------------------
// TMP[e][dd*48 + j=i*3+n] = sum_d feats[e][i][d] * basis[e][d][n*3+dd]
// Block = 16 edges x 16 threads.
// ---------------------------------------------------------------------------
__global__ __launch_bounds__(256)
void tmp_kernel(const float* __restrict__ feats, const float* __restrict__ basis,
                float* __restrict__ TMPg)
{
    __shared__ float sF[16][48];
    __shared__ float sBA[16][27];
    const int tid = threadIdx.x;
    const int el  = tid >> 4;
    const int o   = tid & 15;
    const size_t e = (size_t)blockIdx.x * 16 + el;

    const float* fe = feats + e * 48;
    sF[el][o*3+0] = fe[o*3+0];
    sF[el][o*3+1] = fe[o*3+1];
    sF[el][o*3+2] = fe[o*3+2];
    const float* be = basis + e * 27;
    for (int idx = o; idx < 27; idx += 16) sBA[el][idx] = be[idx];
    __syncthreads();

    float* dst = TMPg + e * 144;
#pragma unroll
    for (int jj = 0; jj < 3; jj++) {
        int j = o + jj * 16;
        int i = j / 3, n = j - i * 3;
        float f0 = sF[el][i*3+0], f1 = sF[el][i*3+1], f2 = sF[el][i*3+2];
#pragma unroll
        for (int dd = 0; dd < 3; dd++) {
            dst[dd * 48 + j] = f0 * sBA[el][n*3 + dd]
                             + f1 * sBA[el][9 + n*3 + dd]
                             + f2 * sBA[el][18 + n*3 + dd];
        }
    }
}

// ---------------------------------------------------------------------------
// fp16 HMMA GEMM (R8-proven). BLO: weight-lo pass. GELU: bias+gelu.
// BM=128 BN=128 BK=32, 3-stage cp.async, 8 warps (2m x 4n), warp 64x32.
// ---------------------------------------------------------------------------
#define STAGE_SZ 24576
#define SMEM_SZ  (3 * STAGE_SZ)

template<int NT, bool GELU, bool AFP32, bool BLO>
__global__ __launch_bounds__(256, 2)
void hgemm(const float* __restrict__ Af, const __half* __restrict__ Ain, int lda,
           const __half* __restrict__ Bh, const __half* __restrict__ Bl, int ldb,
           const float* __restrict__ bias,
           __half* __restrict__ Ch, int ldc)
{
    extern __shared__ __align__(128) char smem_c[];
    const uint32_t smem_u = (uint32_t)__cvta_generic_to_shared(smem_c);

    const int tid  = threadIdx.x;
    const int wid  = tid >> 5;
    const int lane = tid & 31;
    const int wm   = wid >> 2;
    const int wn   = wid & 3;
    const int row0 = blockIdx.x * 128;
    const int cb   = blockIdx.y;

    float acc[4][4][4];
#pragma unroll
    for (int i = 0; i < 4; i++)
#pragma unroll
        for (int j = 0; j < 4; j++)
#pragma unroll
            for (int q = 0; q < 4; q++) acc[i][j][q] = 0.f;

    const int lr0 = tid >> 2, lc0 = tid & 3;
    const int lr1 = (tid + 256) >> 2, lc1 = lc0;

    auto load_tile = [&](int s, int kt) {
        const uint32_t base = smem_u + s * STAGE_SZ;
        if constexpr (!AFP32) {
            CPA16(base + soff(lr0, lc0),
                  Ain + (size_t)(row0 + lr0) * lda + kt * 32 + lc0 * 8);
            CPA16(base + soff(lr1, lc1),
                  Ain + (size_t)(row0 + lr1) * lda + kt * 32 + lc1 * 8);
        }
        CPA16(base + 8192 + soff(lr0, lc0),
              Bh + (size_t)(cb * 128 + lr0) * ldb + kt * 32 + lc0 * 8);
        CPA16(base + 8192 + soff(lr1, lc1),
              Bh + (size_t)(cb * 128 + lr1) * ldb + kt * 32 + lc1 * 8);
        if constexpr (BLO) {
            CPA16(base + 16384 + soff(lr0, lc0),
                  Bl + (size_t)(cb * 128 + lr0) * ldb + kt * 32 + lc0 * 8);
            CPA16(base + 16384 + soff(lr1, lc1),
                  Bl + (size_t)(cb * 128 + lr1) * ldb + kt * 32 + lc1 * 8);
        }
    };

    if constexpr (AFP32) {
        int r = tid >> 1, hf = tid & 1;
        const float4* s4 = (const float4*)(Af + (size_t)(row0 + r) * lda + hf * 16);
        __half2 hx[8];
#pragma unroll
        for (int q = 0; q < 4; q++) {
            float4 v = s4[q];
            hx[2*q]   = __float22half2_rn(make_float2(v.x, v.y));
            hx[2*q+1] = __float22half2_rn(make_float2(v.z, v.w));
        }
        *(uint4*)(smem_c + soff(r, hf * 2))     = *(uint4*)&hx[0];
        *(uint4*)(smem_c + soff(r, hf * 2 + 1)) = *(uint4*)&hx[4];
        load_tile(0, 0);   // B only
        CPA_COMMIT();
    } else {
        load_tile(0, 0);
        CPA_COMMIT();
        if (NT > 1) { load_tile(1, 1); CPA_COMMIT(); }
    }

    const int lr  = (lane & 7) | (((lane >> 3) & 1) << 3);
    const int lkc = lane >> 4;

#pragma unroll 1
    for (int kt = 0; kt < NT; kt++) {
        if (kt + 1 < NT) { CPA_WAIT(1); } else { CPA_WAIT(0); }
        __syncthreads();

        const uint32_t base = smem_u + (kt % 3) * STAGE_SZ;
#pragma unroll
        for (int ks = 0; ks < 2; ks++) {
            const uint32_t xo = ks * 32;
            uint32_t ar[4][4];
#pragma unroll
            for (int mi = 0; mi < 4; mi++)
                LDSM4(ar[mi], (base + soff(wm * 64 + mi * 16 + lr, lkc)) ^ xo);
#pragma unroll
            for (int ng = 0; ng < 2; ng++) {
                uint32_t bh4[4];
                LDSM4(bh4, (base + 8192 + soff(wn * 32 + ng * 16 + lr, lkc)) ^ xo);
#pragma unroll
                for (int mi = 0; mi < 4; mi++) {
                    mma_f16(acc[mi][ng*2],   ar[mi], bh4[0], bh4[2]);
                    mma_f16(acc[mi][ng*2+1], ar[mi], bh4[1], bh4[3]);
                }
                if constexpr (BLO) {
                    uint32_t bl4[4];
                    LDSM4(bl4, (base + 16384 + soff(wn * 32 + ng * 16 + lr, lkc)) ^ xo);
#pragma unroll
                    for (int mi = 0; mi < 4; mi++) {
                        mma_f16(acc[mi][ng*2],   ar[mi], bl4[0], bl4[2]);
                        mma_f16(acc[mi][ng*2+1], ar[mi], bl4[1], bl4[3]);
                    }
                }
            }
        }
        if (kt + 2 < NT) {
            load_tile((kt + 2) % 3, kt + 2);
            CPA_COMMIT();
        }
    }

    const int r = lane >> 2, c2 = lane & 3;
#pragma unroll
    for (int mi = 0; mi < 4; mi++) {
#pragma unroll
        for (int nj = 0; nj < 4; nj++) {
            int row = row0 + wm * 64 + mi * 16 + r;
            int col = cb * 128 + wn * 32 + nj * 8 + c2 * 2;
            float b0 = 0.f, b1 = 0.f;
            if (GELU) { b0 = bias[col]; b1 = bias[col + 1]; }
            float x0 = acc[mi][nj][0] + b0;
            float x1 = acc[mi][nj][1] + b1;
            float x2 = acc[mi][nj][2] + b0;
            float x3 = acc[mi][nj][3] + b1;
            if constexpr (GELU) {
                x0 = gelu_exact(x0); x1 = gelu_exact(x1);
                x2 = gelu_exact(x2); x3 = gelu_exact(x3);
            }
            *(__half2*)&Ch[(size_t)row * ldc + col] =
                __float22half2_rn(make_float2(x0, x1));
            *(__half2*)&Ch[(size_t)(row + 8) * ldc + col] =
                __float22half2_rn(make_float2(x2, x3));
        }
    }
}

// ---------------------------------------------------------------------------
// GEMM3 fused with tail: acc = H2 @ W3h (RP, fp32 in registers), then
// out[e, o, dd] += sum over this CTA's cols of RP[e, gc] * TMP[e][dd][gc%48]
// (o = gc/48). Per-CTA reduction in smem, flushed with global atomicAdd.
// ---------------------------------------------------------------------------
#define SM3F 81920

__global__ __launch_bounds__(256, 2)
void hgemm3_fused(const __half* __restrict__ Ain, const __half* __restrict__ Bh,
                  const float* __restrict__ TMPg, float* __restrict__ out)
{
    extern __shared__ __align__(128) char smem_c[];
    const uint32_t smem_u = (uint32_t)__cvta_generic_to_shared(smem_c);

    const int tid  = threadIdx.x;
    const int wid  = tid >> 5;
    const int lane = tid & 31;
    const int wm   = wid >> 2;
    const int wn   = wid & 3;
    const int row0 = blockIdx.x * 128;
    const int cb   = blockIdx.y;

    float acc[4][4][4];
#pragma unroll
    for (int i = 0; i < 4; i++)
#pragma unroll
        for (int j = 0; j < 4; j++)
#pragma unroll
            for (int q = 0; q < 4; q++) acc[i][j][q] = 0.f;

    const int lr0 = tid >> 2, lc0 = tid & 3;
    const int lr1 = (tid + 256) >> 2, lc1 = lc0;

    auto load_tile = [&](int s, int kt) {
        const uint32_t base = smem_u + s * STAGE_SZ;
        CPA16(base + soff(lr0, lc0),
              Ain + (size_t)(row0 + lr0) * 256 + kt * 32 + lc0 * 8);
        CPA16(base + soff(lr1, lc1),
              Ain + (size_t)(row0 + lr1) * 256 + kt * 32 + lc1 * 8);
        CPA16(base + 8192 + soff(lr0, lc0),
              Bh + (size_t)(cb * 128 + lr0) * 256 + kt * 32 + lc0 * 8);
        CPA16(base + 8192 + soff(lr1, lc1),
              Bh + (size_t)(cb * 128 + lr1) * 256 + kt * 32 + lc1 * 8);
    };

    load_tile(0, 0); CPA_COMMIT();
    load_tile(1, 1); CPA_COMMIT();

    const int lr  = (lane & 7) | (((lane >> 3) & 1) << 3);
    const int lkc = lane >> 4;

#pragma unroll 1
    for (int kt = 0; kt < 8; kt++) {
        if (kt + 1 < 8) { CPA_WAIT(1); } else { CPA_WAIT(0); }
        __syncthreads();

        const uint32_t base = smem_u + (kt % 3) * STAGE_SZ;
#pragma unroll
        for (int ks = 0; ks < 2; ks++) {
            const uint32_t xo = ks * 32;
            uint32_t ar[4][4];
#pragma unroll
            for (int mi = 0; mi < 4; mi++)
                LDSM4(ar[mi], (base + soff(wm * 64 + mi * 16 + lr, lkc)) ^ xo);
#pragma unroll
            for (int ng = 0; ng < 2; ng++) {
                uint32_t bh4[4];
                LDSM4(bh4, (base + 8192 + soff(wn * 32 + ng * 16 + lr, lkc)) ^ xo);
#pragma unroll
                for (int mi = 0; mi < 4; mi++) {
                    mma_f16(acc[mi][ng*2],   ar[mi], bh4[0], bh4[2]);
                    mma_f16(acc[mi][ng*2+1], ar[mi], bh4[1], bh4[3]);
                }
            }
        }
        if (kt + 2 < 8) {
            load_tile((kt + 2) % 3, kt + 2);
            CPA_COMMIT();
        }
    }

    // ---- fused tail epilogue ----
    __syncthreads();                       // stages free now
    float* sTMP = (float*)smem_c;          // 128 edges x 144 = 73728 B (exact)
    float* sOut = (float*)(smem_c + 73728);// 128 x 4(orel) x 3(dd) = 1536 floats

    {   // stage this CTA's TMP slice (coalesced float4 copy)
        const float4* src = (const float4*)(TMPg + (size_t)row0 * 144);
        float4* dst = (float4*)sTMP;
#pragma unroll
        for (int it = 0; it < 18; it++) dst[tid + it * 256] = src[tid + it * 256];
    }
#pragma unroll
    for (int it = 0; it < 6; it++) sOut[tid + it * 256] = 0.f;
    __syncthreads();

    const int r4 = lane >> 2, c2 = lane & 3;
    const int o_min = (cb * 128) / 48;
    int jj8[8], ss8[8];
    {
        int basec = cb * 128 + wn * 32 + c2 * 2;
#pragma unroll
        for (int t = 0; t < 8; t++) {
            int gc = basec + (t >> 1) * 8 + (t & 1);
            int o  = gc / 48;
            jj8[t] = gc - o * 48;
            ss8[t] = o - o_min;     // 0..3, at most 2 distinct per thread
        }
    }
    const int s0 = ss8[0];

#pragma unroll
    for (int mi = 0; mi < 4; mi++) {
        int rA = wm * 64 + mi * 16 + r4;
        const float* tpA = sTMP + rA * 144;
        const float* tpB = sTMP + (rA + 8) * 144;
        float pA0[3] = {0,0,0}, pA1[3] = {0,0,0};
        float pB0[3] = {0,0,0}, pB1[3] = {0,0,0};
#pragma unroll
        for (int nj = 0; nj < 4; nj++)
#pragma unroll
        for (int c = 0; c < 2; c++) {
            int t = nj * 2 + c;
            int j = jj8[t];
            bool hi = (ss8[t] != s0);
            float vA = acc[mi][nj][c];
            float vB = acc[mi][nj][2 + c];
#pragma unroll
            for (int dd = 0; dd < 3; dd++) {
                float tv = tpA[dd * 48 + j];
                float uv = tpB[dd * 48 + j];
                if (hi) { pA1[dd] = fmaf(vA, tv, pA1[dd]);
                          pB1[dd] = fmaf(vB, uv, pB1[dd]); }
                else    { pA0[dd] = fmaf(vA, tv, pA0[dd]);
                          pB0[dd] = fmaf(vB, uv, pB0[dd]); }
            }
        }
#pragma unroll
        for (int dd = 0; dd < 3; dd++) {
            atomicAdd(&sOut[(rA * 4 + s0) * 3 + dd], pA0[dd]);
            atomicAdd(&sOut[((rA + 8) * 4 + s0) * 3 + dd], pB0[dd]);
            if (s0 + 1 < 4) {
                if (pA1[dd] != 0.f)
                    atomicAdd(&sOut[(rA * 4 + s0 + 1) * 3 + dd], pA1[dd]);
                if (pB1[dd] != 0.f)
                    atomicAdd(&sOut[((rA + 8) * 4 + s0 + 1) * 3 + dd], pB1[dd]);
            }
        }
    }
    __syncthreads();

    // flush per-CTA partials to global (cross-CTA overlap only at o straddles)
#pragma unroll
    for (int it = 0; it < 6; it++) {
        int idx = tid + it * 256;
        float v = sOut[idx];
        int e_l  = idx / 12, rest = idx - e_l * 12;
        int orel = rest / 3,  dd  = rest - orel * 3;
        int o = o_min + orel;
        if (o < 16 && v != 0.f)
            atomicAdd(&out[(size_t)(row0 + e_l) * 48 + o * 3 + dd], v);
    }
}

// ---------------------------------------------------------------------------
extern "C" void kernel_launch(void* const* d_in, const int* in_sizes, int n_in,
                              void* d_out, int out_size)
{
    const float* edges = (const float*)d_in[0];
    const float* feats = (const float*)d_in[1];
    const float* basis = (const float*)d_in[2];
    const float* W1    = (const float*)d_in[3];
    const float* b1    = (const float*)d_in[4];
    const float* W2    = (const float*)d_in[5];
    const float* b2    = (const float*)d_in[6];
    const float* W3    = (const float*)d_in[7];
    float* out = (float*)d_out;

    __half *W1h, *W1l, *W2h, *W3h, *H1, *H2;
    float *TMPg;
    cudaGetSymbolAddress((void**)&W1h, g_W1h);
    cudaGetSymbolAddress((void**)&W1l, g_W1l);
    cudaGetSymbolAddress((void**)&W2h, g_W2h);
    cudaGetSymbolAddress((void**)&W3h, g_W3h);
    cudaGetSymbolAddress((void**)&H1,  g_H1);
    cudaGetSymbolAddress((void**)&H2,  g_H2);
    cudaGetSymbolAddress((void**)&TMPg, g_TMP);

    cudaFuncSetAttribute(hgemm<1, true, true, true>,
                         cudaFuncAttributeMaxDynamicSharedMemorySize, SMEM_SZ);
    cudaFuncSetAttribute(hgemm<8, true, false, false>,
                         cudaFuncAttributeMaxDynamicSharedMemorySize, SMEM_SZ);
    cudaFuncSetAttribute(hgemm3_fused,
                         cudaFuncAttributeMaxDynamicSharedMemorySize, SM3F);

    prep_weight<<<(256 * 32 + 255) / 256, 256>>>(W1, 32, 256, 256, 0, W1h, W1l);
    prep_weight<<<(256 * 256 + 255) / 256, 256>>>(W2, 256, 256, 256, 0, W2h, nullptr);
    prep_weight<<<(768 * 256 + 255) / 256, 256>>>(W3, 256, 768, 1536, W3OFF, W3h, nullptr);

    dim3 blk(256);
    // out = 0 (atomics accumulate into it); E*48 floats = 786432 float4
    zero_out<<<786432 / 256, 256>>>((float4*)out);
    // TMP[e][dd][j]
    tmp_kernel<<<E_TOTAL / 16, blk>>>(feats, basis, TMPg);
    // layer 1: gelu(edges @ W1 + b1) -> H1 (2-pass exact weights)
    hgemm<1, true, true, true><<<dim3(E_TOTAL / 128, 2), blk, SMEM_SZ>>>(
        edges, nullptr, 32, W1h, W1l, 32, b1, H1, 256);
    // layer 2: gelu(H1 @ W2 + b2) -> H2
    hgemm<8, true, false, false><<<dim3(E_TOTAL / 128, 2), blk, SMEM_SZ>>>(
        nullptr, H1, 256, W2h, nullptr, 256, b2, H2, 256);
    // layer 3 + tail fused
    hgemm3_fused<<<dim3(E_TOTAL / 128, 6), blk, SM3F>>>(H2, W3h, TMPg, out);
}

// round 13
// speedup vs baseline: 1.5619x; 1.5619x over previous
#include <cuda_runtime.h>
#include <cuda_fp16.h>
#include <math.h>
#include <stdint.h>

#define E_TOTAL 65536     // B*N*K
#define W3OFF   768       // SPLIT_OFF
#define RPN     768       // SPLIT_SZ

// ---- device scratch ----
__device__ __half g_W1h[256 * 32],  g_W1l[256 * 32];
__device__ __half g_W2h[256 * 256];
__device__ __half g_W3h[768 * 256];
__device__ __half g_H1[(size_t)E_TOTAL * 256];
__device__ __half g_H2[(size_t)E_TOTAL * 256];
__device__ __half g_RP[(size_t)E_TOTAL * RPN];   // fp16 RP (100 MB)

__device__ __forceinline__ float gelu_exact(float x) {
    return 0.5f * x * (1.0f + erff(x * 0.70710678118654752440f));
}

// ---------------------------------------------------------------------------
#define CPA16(dst_u32, src_ptr) \
    asm volatile("cp.async.cg.shared.global [%0], [%1], 16;" :: "r"(dst_u32), "l"(src_ptr))
#define CPA_COMMIT() asm volatile("cp.async.commit_group;" ::: "memory")
#define CPA_WAIT(n)  asm volatile("cp.async.wait_group %0;" :: "n"(n) : "memory")

#define LDSM4(R, addr)                                                        \
    asm volatile("ldmatrix.sync.aligned.m8n8.x4.shared.b16 {%0,%1,%2,%3}, [%4];" \
                 : "=r"((R)[0]), "=r"((R)[1]), "=r"((R)[2]), "=r"((R)[3])     \
                 : "r"(addr))

__device__ __forceinline__ void mma_f16(float* d, const uint32_t* a,
                                        uint32_t b0, uint32_t b1) {
    asm volatile(
        "mma.sync.aligned.m16n8k16.row.col.f32.f16.f16.f32 "
        "{%0,%1,%2,%3}, {%4,%5,%6,%7}, {%8,%9}, {%0,%1,%2,%3};"
        : "+f"(d[0]), "+f"(d[1]), "+f"(d[2]), "+f"(d[3])
        : "r"(a[0]), "r"(a[1]), "r"(a[2]), "r"(a[3]), "r"(b0), "r"(b1));
}

// swizzled byte offset for 64B rows (4 chunks of 16B); conflict-free for
// cp.async stores AND ldmatrix phases (validated R4/R6-R9).
__device__ __forceinline__ uint32_t soff(int r, int c) {
    return (uint32_t)((r * 4 + (c ^ ((r >> 1) & 3))) << 4);
}

// ---------------------------------------------------------------------------
__global__ void prep_weight(const float* __restrict__ W, int K, int N, int ldw,
                            int coff, __half* __restrict__ hi, __half* __restrict__ lo)
{
    int idx = blockIdx.x * 256 + threadIdx.x;
    if (idx >= N * K) return;
    int n = idx / K, k = idx - n * K;
    float v = W[(size_t)k * ldw + coff + n];
    __half h = __float2half_rn(v);
    hi[idx] = h;
    if (lo) lo[idx] = __float2half_rn(v - __half2float(h));
}

// ---------------------------------------------------------------------------
// fp16 HMMA GEMM (R8-proven). BLO: weight-lo pass. GELU: bias+gelu.
// BM=128 BN=128 BK=32, 3-stage cp.async, 8 warps (2m x 4n), warp 64x32.
// ---------------------------------------------------------------------------
#define STAGE_SZ 24576
#define SMEM_SZ  (3 * STAGE_SZ)

template<int NT, bool GELU, bool AFP32, bool BLO>
__global__ __launch_bounds__(256, 2)
void hgemm(const float* __restrict__ Af, const __half* __restrict__ Ain, int lda,
           const __half* __restrict__ Bh, const __half* __restrict__ Bl, int ldb,
           const float* __restrict__ bias,
           __half* __restrict__ Ch, int ldc)
{
    extern __shared__ __align__(128) char smem_c[];
    const uint32_t smem_u = (uint32_t)__cvta_generic_to_shared(smem_c);

    const int tid  = threadIdx.x;
    const int wid  = tid >> 5;
    const int lane = tid & 31;
    const int wm   = wid >> 2;
    const int wn   = wid & 3;
    const int row0 = blockIdx.x * 128;
    const int cb   = blockIdx.y;

    float acc[4][4][4];
#pragma unroll
    for (int i = 0; i < 4; i++)
#pragma unroll
        for (int j = 0; j < 4; j++)
#pragma unroll
            for (int q = 0; q < 4; q++) acc[i][j][q] = 0.f;

    const int lr0 = tid >> 2, lc0 = tid & 3;
    const int lr1 = (tid + 256) >> 2, lc1 = lc0;

    auto load_tile = [&](int s, int kt) {
        const uint32_t base = smem_u + s * STAGE_SZ;
        if constexpr (!AFP32) {
            CPA16(base + soff(lr0, lc0),
                  Ain + (size_t)(row0 + lr0) * lda + kt * 32 + lc0 * 8);
            CPA16(base + soff(lr1, lc1),
                  Ain + (size_t)(row0 + lr1) * lda + kt * 32 + lc1 * 8);
        }
        CPA16(base + 8192 + soff(lr0, lc0),
              Bh + (size_t)(cb * 128 + lr0) * ldb + kt * 32 + lc0 * 8);
        CPA16(base + 8192 + soff(lr1, lc1),
              Bh + (size_t)(cb * 128 + lr1) * ldb + kt * 32 + lc1 * 8);
        if constexpr (BLO) {
            CPA16(base + 16384 + soff(lr0, lc0),
                  Bl + (size_t)(cb * 128 + lr0) * ldb + kt * 32 + lc0 * 8);
            CPA16(base + 16384 + soff(lr1, lc1),
                  Bl + (size_t)(cb * 128 + lr1) * ldb + kt * 32 + lc1 * 8);
        }
    };

    if constexpr (AFP32) {
        int r = tid >> 1, hf = tid & 1;
        const float4* s4 = (const float4*)(Af + (size_t)(row0 + r) * lda + hf * 16);
        __half2 hx[8];
#pragma unroll
        for (int q = 0; q < 4; q++) {
            float4 v = s4[q];
            hx[2*q]   = __float22half2_rn(make_float2(v.x, v.y));
            hx[2*q+1] = __float22half2_rn(make_float2(v.z, v.w));
        }
        *(uint4*)(smem_c + soff(r, hf * 2))     = *(uint4*)&hx[0];
        *(uint4*)(smem_c + soff(r, hf * 2 + 1)) = *(uint4*)&hx[4];
        load_tile(0, 0);   // B only
        CPA_COMMIT();
    } else {
        load_tile(0, 0);
        CPA_COMMIT();
        if (NT > 1) { load_tile(1, 1); CPA_COMMIT(); }
    }

    const int lr  = (lane & 7) | (((lane >> 3) & 1) << 3);
    const int lkc = lane >> 4;

#pragma unroll 1
    for (int kt = 0; kt < NT; kt++) {
        if (kt + 1 < NT) { CPA_WAIT(1); } else { CPA_WAIT(0); }
        __syncthreads();

        const uint32_t base = smem_u + (kt % 3) * STAGE_SZ;
#pragma unroll
        for (int ks = 0; ks < 2; ks++) {
            const uint32_t xo = ks * 32;
            uint32_t ar[4][4];
#pragma unroll
            for (int mi = 0; mi < 4; mi++)
                LDSM4(ar[mi], (base + soff(wm * 64 + mi * 16 + lr, lkc)) ^ xo);
#pragma unroll
            for (int ng = 0; ng < 2; ng++) {
                uint32_t bh4[4];
                LDSM4(bh4, (base + 8192 + soff(wn * 32 + ng * 16 + lr, lkc)) ^ xo);
#pragma unroll
                for (int mi = 0; mi < 4; mi++) {
                    mma_f16(acc[mi][ng*2],   ar[mi], bh4[0], bh4[2]);
                    mma_f16(acc[mi][ng*2+1], ar[mi], bh4[1], bh4[3]);
                }
                if constexpr (BLO) {
                    uint32_t bl4[4];
                    LDSM4(bl4, (base + 16384 + soff(wn * 32 + ng * 16 + lr, lkc)) ^ xo);
#pragma unroll
                    for (int mi = 0; mi < 4; mi++) {
                        mma_f16(acc[mi][ng*2],   ar[mi], bl4[0], bl4[2]);
                        mma_f16(acc[mi][ng*2+1], ar[mi], bl4[1], bl4[3]);
                    }
                }
            }
        }
        if (kt + 2 < NT) {
            load_tile((kt + 2) % 3, kt + 2);
            CPA_COMMIT();
        }
    }

    const int r = lane >> 2, c2 = lane & 3;
#pragma unroll
    for (int mi = 0; mi < 4; mi++) {
#pragma unroll
        for (int nj = 0; nj < 4; nj++) {
            int row = row0 + wm * 64 + mi * 16 + r;
            int col = cb * 128 + wn * 32 + nj * 8 + c2 * 2;
            float b0 = 0.f, b1 = 0.f;
            if (GELU) { b0 = bias[col]; b1 = bias[col + 1]; }
            float x0 = acc[mi][nj][0] + b0;
            float x1 = acc[mi][nj][1] + b1;
            float x2 = acc[mi][nj][2] + b0;
            float x3 = acc[mi][nj][3] + b1;
            if constexpr (GELU) {
                x0 = gelu_exact(x0); x1 = gelu_exact(x1);
                x2 = gelu_exact(x2); x3 = gelu_exact(x3);
            }
            *(__half2*)&Ch[(size_t)row * ldc + col] =
                __float22half2_rn(make_float2(x0, x1));
            *(__half2*)&Ch[(size_t)(row + 8) * ldc + col] =
                __float22half2_rn(make_float2(x2, x3));
        }
    }
}

// ---------------------------------------------------------------------------
// Tail (R9-proven): tmp stored transposed [dd][j] for vectorized loads.
//   tmp[dd][j=i*3+n] = sum_d f[i,d] * basis[d, n*3+dd]
//   out[o][dd]       = sum_j RP[e, o*48+j] * tmp[dd][j]
// Block = 16 edges x 16 threads. RP is fp16.
// ---------------------------------------------------------------------------
__global__ __launch_bounds__(256)
void tail_kernel(const __half* __restrict__ RP, const float* __restrict__ feats,
                 const float* __restrict__ basis, float* __restrict__ out)
{
    __shared__ __align__(16) float sT[16][3][52];
    __shared__ float sF[16][48];
    __shared__ float sBA[16][27];

    const int tid = threadIdx.x;
    const int el  = tid >> 4;
    const int o   = tid & 15;
    const size_t e = (size_t)blockIdx.x * 16 + el;

    const float* fe = feats + e * 48;
    sF[el][o*3+0] = fe[o*3+0];
    sF[el][o*3+1] = fe[o*3+1];
    sF[el][o*3+2] = fe[o*3+2];
    const float* be = basis + e * 27;
    for (int idx = o; idx < 27; idx += 16) sBA[el][idx] = be[idx];
    __syncthreads();

#pragma unroll
    for (int jj = 0; jj < 3; jj++) {
        int j = o + jj * 16;
        int i = j / 3, n = j - i * 3;
        float f0 = sF[el][i*3+0], f1 = sF[el][i*3+1], f2 = sF[el][i*3+2];
#pragma unroll
        for (int dd = 0; dd < 3; dd++) {
            sT[el][dd][j] = f0 * sBA[el][n*3 + dd]
                          + f1 * sBA[el][9 + n*3 + dd]
                          + f2 * sBA[el][18 + n*3 + dd];
        }
    }
    __syncthreads();

    const uint4* rp4 = (const uint4*)(RP + e * RPN + o * 48);
    const float* t0 = &sT[el][0][0];
    const float* t1 = &sT[el][1][0];
    const float* t2 = &sT[el][2][0];
    float s0 = 0.f, s1 = 0.f, s2 = 0.f;
#pragma unroll
    for (int q = 0; q < 6; q++) {
        uint4 u = rp4[q];
        const __half2* hp = (const __half2*)&u;
        float2 f01 = __half22float2(hp[0]);
        float2 f23 = __half22float2(hp[1]);
        float2 f45 = __half22float2(hp[2]);
        float2 f67 = __half22float2(hp[3]);
        float4 a0 = *(const float4*)&t0[q*8];
        float4 a1 = *(const float4*)&t0[q*8+4];
        s0 = fmaf(f01.x, a0.x, s0); s0 = fmaf(f01.y, a0.y, s0);
        s0 = fmaf(f23.x, a0.z, s0); s0 = fmaf(f23.y, a0.w, s0);
        s0 = fmaf(f45.x, a1.x, s0); s0 = fmaf(f45.y, a1.y, s0);
        s0 = fmaf(f67.x, a1.z, s0); s0 = fmaf(f67.y, a1.w, s0);
        float4 b0 = *(const float4*)&t1[q*8];
        float4 b1 = *(const float4*)&t1[q*8+4];
        s1 = fmaf(f01.x, b0.x, s1); s1 = fmaf(f01.y, b0.y, s1);
        s1 = fmaf(f23.x, b0.z, s1); s1 = fmaf(f23.y, b0.w, s1);
        s1 = fmaf(f45.x, b1.x, s1); s1 = fmaf(f45.y, b1.y, s1);
        s1 = fmaf(f67.x, b1.z, s1); s1 = fmaf(f67.y, b1.w, s1);
        float4 g0 = *(const float4*)&t2[q*8];
        float4 g1 = *(const float4*)&t2[q*8+4];
        s2 = fmaf(f01.x, g0.x, s2); s2 = fmaf(f01.y, g0.y, s2);
        s2 = fmaf(f23.x, g0.z, s2); s2 = fmaf(f23.y, g0.w, s2);
        s2 = fmaf(f45.x, g1.x, s2); s2 = fmaf(f45.y, g1.y, s2);
        s2 = fmaf(f67.x, g1.z, s2); s2 = fmaf(f67.y, g1.w, s2);
    }
    float* op = out + (e * 16 + o) * 3;
    op[0] = s0; op[1] = s1; op[2] = s2;
}

// ---------------------------------------------------------------------------
extern "C" void kernel_launch(void* const* d_in, const int* in_sizes, int n_in,
                              void* d_out, int out_size)
{
    const float* edges = (const float*)d_in[0];
    const float* feats = (const float*)d_in[1];
    const float* basis = (const float*)d_in[2];
    const float* W1    = (const float*)d_in[3];
    const float* b1    = (const float*)d_in[4];
    const float* W2    = (const float*)d_in[5];
    const float* b2    = (const float*)d_in[6];
    const float* W3    = (const float*)d_in[7];
    float* out = (float*)d_out;

    __half *W1h, *W1l, *W2h, *W3h, *H1, *H2, *RP;
    cudaGetSymbolAddress((void**)&W1h, g_W1h);
    cudaGetSymbolAddress((void**)&W1l, g_W1l);
    cudaGetSymbolAddress((void**)&W2h, g_W2h);
    cudaGetSymbolAddress((void**)&W3h, g_W3h);
    cudaGetSymbolAddress((void**)&H1,  g_H1);
    cudaGetSymbolAddress((void**)&H2,  g_H2);
    cudaGetSymbolAddress((void**)&RP,  g_RP);

    cudaFuncSetAttribute(hgemm<1, true,  true,  true>,
                         cudaFuncAttributeMaxDynamicSharedMemorySize, SMEM_SZ);
    cudaFuncSetAttribute(hgemm<8, true,  false, false>,
                         cudaFuncAttributeMaxDynamicSharedMemorySize, SMEM_SZ);
    cudaFuncSetAttribute(hgemm<8, false, false, false>,
                         cudaFuncAttributeMaxDynamicSharedMemorySize, SMEM_SZ);

    // weight prep (transpose; hi/lo only for W1)
    prep_weight<<<(256 * 32 + 255) / 256, 256>>>(W1, 32, 256, 256, 0, W1h, W1l);
    prep_weight<<<(256 * 256 + 255) / 256, 256>>>(W2, 256, 256, 256, 0, W2h, nullptr);
    prep_weight<<<(768 * 256 + 255) / 256, 256>>>(W3, 256, 768, 1536, W3OFF, W3h, nullptr);

    dim3 blk(256);
    // layer 1: gelu(edges @ W1 + b1) -> H1 fp16  (2-pass exact weights)
    hgemm<1, true, true, true><<<dim3(E_TOTAL / 128, 2), blk, SMEM_SZ>>>(
        edges, nullptr, 32, W1h, W1l, 32, b1, H1, 256);
    // layer 2: gelu(H1 @ W2 + b2) -> H2 fp16  (hi-only)
    hgemm<8, true, false, false><<<dim3(E_TOTAL / 128, 2), blk, SMEM_SZ>>>(
        nullptr, H1, 256, W2h, nullptr, 256, b2, H2, 256);
    // layer 3: H2 @ W3[:,768:1536] -> RP fp16  (hi-only, 6 chunks of 128)
    hgemm<8, false, false, false><<<dim3(E_TOTAL / 128, 6), blk, SMEM_SZ>>>(
        nullptr, H2, 256, W3h, nullptr, 256, nullptr, RP, RPN);
    // tail (fast transposed-tmp version)
    tail_kernel<<<E_TOTAL / 16, blk>>>(RP, feats, basis, out);
}

// round 14
// speedup vs baseline: 1.6016x; 1.0254x over previous
#include <cuda_runtime.h>
#include <cuda_fp16.h>
#include <math.h>
#include <stdint.h>

#define E_TOTAL 65536     // B*N*K
#define W3OFF   768       // SPLIT_OFF
#define RPN     768       // SPLIT_SZ

// ---- device scratch ----
__device__ __half g_W1h[256 * 32],  g_W1l[256 * 32];
__device__ __half g_W2h[256 * 256];
__device__ __half g_W3h[768 * 256];
__device__ __half g_H1[(size_t)E_TOTAL * 256];
__device__ __half g_H2[(size_t)E_TOTAL * 256];
__device__ __half g_RP[(size_t)E_TOTAL * RPN];   // fp16 RP (100 MB)

__device__ __forceinline__ float gelu_exact(float x) {
    return 0.5f * x * (1.0f + erff(x * 0.70710678118654752440f));
}

// ---------------------------------------------------------------------------
#define CPA16(dst_u32, src_ptr) \
    asm volatile("cp.async.cg.shared.global [%0], [%1], 16;" :: "r"(dst_u32), "l"(src_ptr))
#define CPA_COMMIT() asm volatile("cp.async.commit_group;" ::: "memory")
#define CPA_WAIT(n)  asm volatile("cp.async.wait_group %0;" :: "n"(n) : "memory")

#define LDSM4(R, addr)                                                        \
    asm volatile("ldmatrix.sync.aligned.m8n8.x4.shared.b16 {%0,%1,%2,%3}, [%4];" \
                 : "=r"((R)[0]), "=r"((R)[1]), "=r"((R)[2]), "=r"((R)[3])     \
                 : "r"(addr))

__device__ __forceinline__ void mma_f16(float* d, const uint32_t* a,
                                        uint32_t b0, uint32_t b1) {
    asm volatile(
        "mma.sync.aligned.m16n8k16.row.col.f32.f16.f16.f32 "
        "{%0,%1,%2,%3}, {%4,%5,%6,%7}, {%8,%9}, {%0,%1,%2,%3};"
        : "+f"(d[0]), "+f"(d[1]), "+f"(d[2]), "+f"(d[3])
        : "r"(a[0]), "r"(a[1]), "r"(a[2]), "r"(a[3]), "r"(b0), "r"(b1));
}

// swizzled byte offset for 64B rows (4 chunks of 16B); conflict-free for
// cp.async stores AND ldmatrix phases (validated R4/R6-R13).
__device__ __forceinline__ uint32_t soff(int r, int c) {
    return (uint32_t)((r * 4 + (c ^ ((r >> 1) & 3))) << 4);
}

// ---------------------------------------------------------------------------
// merged weight prep: W1 (hi+lo, transposed), W2 (hi), W3 slice (hi)
// ---------------------------------------------------------------------------
__global__ void prep_all(const float* __restrict__ W1, const float* __restrict__ W2,
                         const float* __restrict__ W3,
                         __half* __restrict__ W1h, __half* __restrict__ W1l,
                         __half* __restrict__ W2h, __half* __restrict__ W3h)
{
    int idx = blockIdx.x * 256 + threadIdx.x;
    if (idx < 8192) {                          // W1: [256 n][32 k]
        int n = idx >> 5, k = idx & 31;
        float v = W1[k * 256 + n];
        __half h = __float2half_rn(v);
        W1h[idx] = h;
        W1l[idx] = __float2half_rn(v - __half2float(h));
    } else if (idx < 8192 + 65536) {           // W2: [256 n][256 k]
        int i = idx - 8192;
        int n = i >> 8, k = i & 255;
        W2h[i] = __float2half_rn(W2[k * 256 + n]);
    } else if (idx < 8192 + 65536 + 196608) {  // W3 slice: [768 n][256 k]
        int i = idx - 73728;
        int n = i >> 8, k = i & 255;
        W3h[i] = __float2half_rn(W3[(size_t)k * 1536 + W3OFF + n]);
    }
}

// ---------------------------------------------------------------------------
// GEMM1 multi-tile: grid (E/512, 2). Each CTA: 4 row-tiles of 128, 2-deep
// cp.async pipeline on fp32 edges; W1 hi/lo loaded once.
// smem: eF32[2]@0 (2x16K, XOR-swizzled 16B chunks), eH@32768 (8K),
//       W1h@40960, W1l@49152.  total 57344.
// ---------------------------------------------------------------------------
#define SM1 57344

__global__ __launch_bounds__(256, 2)
void hgemm1(const float* __restrict__ edges,
            const __half* __restrict__ W1h, const __half* __restrict__ W1l,
            const float* __restrict__ b1, __half* __restrict__ H1)
{
    extern __shared__ __align__(128) char smem_c[];
    const uint32_t smem_u = (uint32_t)__cvta_generic_to_shared(smem_c);

    const int tid  = threadIdx.x;
    const int wid  = tid >> 5;
    const int lane = tid & 31;
    const int wm   = wid >> 2;
    const int wn   = wid & 3;
    const int cb   = blockIdx.y;
    const int tile0 = blockIdx.x * 4;

    const int lr0 = tid >> 2, lc0 = tid & 3;
    const int lr1 = (tid + 256) >> 2, lc1 = lc0;

    auto issue_edges = [&](int buf, int rt) {
        int row0 = (tile0 + rt) * 128;
#pragma unroll
        for (int i = 0; i < 4; i++) {
            int idx = tid + i * 256;            // 1024 16B chunks
            int r = idx >> 3, c = idx & 7;
            CPA16(smem_u + buf * 16384 + (uint32_t)(r * 128 + (c ^ (r & 7)) * 16),
                  edges + (size_t)(row0 + r) * 32 + c * 4);
        }
    };
    auto issue_w1 = [&]() {
        CPA16(smem_u + 40960 + soff(lr0, lc0), W1h + (size_t)(cb * 128 + lr0) * 32 + lc0 * 8);
        CPA16(smem_u + 40960 + soff(lr1, lc1), W1h + (size_t)(cb * 128 + lr1) * 32 + lc1 * 8);
        CPA16(smem_u + 49152 + soff(lr0, lc0), W1l + (size_t)(cb * 128 + lr0) * 32 + lc0 * 8);
        CPA16(smem_u + 49152 + soff(lr1, lc1), W1l + (size_t)(cb * 128 + lr1) * 32 + lc1 * 8);
    };

    issue_edges(0, 0);
    issue_w1();
    CPA_COMMIT();
    issue_edges(1, 1);
    CPA_COMMIT();

    const int lr  = (lane & 7) | (((lane >> 3) & 1) << 3);
    const int lkc = lane >> 4;
    const int r4  = lane >> 2, c2 = lane & 3;
    const int cvr = tid >> 1, cvh = tid & 1;   // convert mapping

#pragma unroll 1
    for (int rt = 0; rt < 4; rt++) {
        if (rt + 1 < 4) { CPA_WAIT(1); } else { CPA_WAIT(0); }
        __syncthreads();

        // convert fp32 staging -> swizzled fp16 eH
        {
            const char* src = smem_c + (rt & 1) * 16384 + cvr * 128;
            __half2 hx[8];
#pragma unroll
            for (int q = 0; q < 4; q++) {
                int ch = cvh * 4 + q;
                float4 v = *(const float4*)(src + ((ch ^ (cvr & 7)) * 16));
                hx[2*q]   = __float22half2_rn(make_float2(v.x, v.y));
                hx[2*q+1] = __float22half2_rn(make_float2(v.z, v.w));
            }
            *(uint4*)(smem_c + 32768 + soff(cvr, cvh * 2))     = *(uint4*)&hx[0];
            *(uint4*)(smem_c + 32768 + soff(cvr, cvh * 2 + 1)) = *(uint4*)&hx[4];
        }
        __syncthreads();

        float acc[4][4][4];
#pragma unroll
        for (int i = 0; i < 4; i++)
#pragma unroll
            for (int j = 0; j < 4; j++)
#pragma unroll
                for (int q = 0; q < 4; q++) acc[i][j][q] = 0.f;

#pragma unroll
        for (int ks = 0; ks < 2; ks++) {
            const uint32_t xo = ks * 32;
            uint32_t ar[4][4];
#pragma unroll
            for (int mi = 0; mi < 4; mi++)
                LDSM4(ar[mi], (smem_u + 32768 + soff(wm * 64 + mi * 16 + lr, lkc)) ^ xo);
#pragma unroll
            for (int ng = 0; ng < 2; ng++) {
                uint32_t bh4[4], bl4[4];
                LDSM4(bh4, (smem_u + 40960 + soff(wn * 32 + ng * 16 + lr, lkc)) ^ xo);
                LDSM4(bl4, (smem_u + 49152 + soff(wn * 32 + ng * 16 + lr, lkc)) ^ xo);
#pragma unroll
                for (int mi = 0; mi < 4; mi++) {
                    mma_f16(acc[mi][ng*2],   ar[mi], bh4[0], bh4[2]);
                    mma_f16(acc[mi][ng*2+1], ar[mi], bh4[1], bh4[3]);
                    mma_f16(acc[mi][ng*2],   ar[mi], bl4[0], bl4[2]);
                    mma_f16(acc[mi][ng*2+1], ar[mi], bl4[1], bl4[3]);
                }
            }
        }

        // epilogue: bias + gelu -> H1
        int row0 = (tile0 + rt) * 128;
#pragma unroll
        for (int mi = 0; mi < 4; mi++) {
#pragma unroll
            for (int nj = 0; nj < 4; nj++) {
                int row = row0 + wm * 64 + mi * 16 + r4;
                int col = cb * 128 + wn * 32 + nj * 8 + c2 * 2;
                float bb0 = b1[col], bb1 = b1[col + 1];
                float x0 = gelu_exact(acc[mi][nj][0] + bb0);
                float x1 = gelu_exact(acc[mi][nj][1] + bb1);
                float x2 = gelu_exact(acc[mi][nj][2] + bb0);
                float x3 = gelu_exact(acc[mi][nj][3] + bb1);
                *(__half2*)&H1[(size_t)row * 256 + col] =
                    __float22half2_rn(make_float2(x0, x1));
                *(__half2*)&H1[(size_t)(row + 8) * 256 + col] =
                    __float22half2_rn(make_float2(x2, x3));
            }
        }

        if (rt + 2 < 4) {
            issue_edges(rt & 1, rt + 2);
            CPA_COMMIT();
        }
    }
}

// ---------------------------------------------------------------------------
// fp16 HMMA GEMM (R8-proven) for layers 2 and 3.
// BM=128 BN=128 BK=32, 3-stage cp.async, 8 warps (2m x 4n), warp 64x32.
// ---------------------------------------------------------------------------
#define STAGE_SZ 24576
#define SMEM_SZ  (3 * STAGE_SZ)

template<int NT, bool GELU>
__global__ __launch_bounds__(256, 2)
void hgemm(const __half* __restrict__ Ain, int lda,
           const __half* __restrict__ Bh, int ldb,
           const float* __restrict__ bias,
           __half* __restrict__ Ch, int ldc)
{
    extern __shared__ __align__(128) char smem_c[];
    const uint32_t smem_u = (uint32_t)__cvta_generic_to_shared(smem_c);

    const int tid  = threadIdx.x;
    const int wid  = tid >> 5;
    const int lane = tid & 31;
    const int wm   = wid >> 2;
    const int wn   = wid & 3;
    const int row0 = blockIdx.x * 128;
    const int cb   = blockIdx.y;

    float acc[4][4][4];
#pragma unroll
    for (int i = 0; i < 4; i++)
#pragma unroll
        for (int j = 0; j < 4; j++)
#pragma unroll
            for (int q = 0; q < 4; q++) acc[i][j][q] = 0.f;

    const int lr0 = tid >> 2, lc0 = tid & 3;
    const int lr1 = (tid + 256) >> 2, lc1 = lc0;

    auto load_tile = [&](int s, int kt) {
        const uint32_t base = smem_u + s * STAGE_SZ;
        CPA16(base + soff(lr0, lc0),
              Ain + (size_t)(row0 + lr0) * lda + kt * 32 + lc0 * 8);
        CPA16(base + soff(lr1, lc1),
              Ain + (size_t)(row0 + lr1) * lda + kt * 32 + lc1 * 8);
        CPA16(base + 8192 + soff(lr0, lc0),
              Bh + (size_t)(cb * 128 + lr0) * ldb + kt * 32 + lc0 * 8);
        CPA16(base + 8192 + soff(lr1, lc1),
              Bh + (size_t)(cb * 128 + lr1) * ldb + kt * 32 + lc1 * 8);
    };

    load_tile(0, 0); CPA_COMMIT();
    load_tile(1, 1); CPA_COMMIT();

    const int lr  = (lane & 7) | (((lane >> 3) & 1) << 3);
    const int lkc = lane >> 4;

#pragma unroll 1
    for (int kt = 0; kt < NT; kt++) {
        if (kt + 1 < NT) { CPA_WAIT(1); } else { CPA_WAIT(0); }
        __syncthreads();

        const uint32_t base = smem_u + (kt % 3) * STAGE_SZ;
#pragma unroll
        for (int ks = 0; ks < 2; ks++) {
            const uint32_t xo = ks * 32;
            uint32_t ar[4][4];
#pragma unroll
            for (int mi = 0; mi < 4; mi++)
                LDSM4(ar[mi], (base + soff(wm * 64 + mi * 16 + lr, lkc)) ^ xo);
#pragma unroll
            for (int ng = 0; ng < 2; ng++) {
                uint32_t bh4[4];
                LDSM4(bh4, (base + 8192 + soff(wn * 32 + ng * 16 + lr, lkc)) ^ xo);
#pragma unroll
                for (int mi = 0; mi < 4; mi++) {
                    mma_f16(acc[mi][ng*2],   ar[mi], bh4[0], bh4[2]);
                    mma_f16(acc[mi][ng*2+1], ar[mi], bh4[1], bh4[3]);
                }
            }
        }
        if (kt + 2 < NT) {
            load_tile((kt + 2) % 3, kt + 2);
            CPA_COMMIT();
        }
    }

    const int r = lane >> 2, c2 = lane & 3;
#pragma unroll
    for (int mi = 0; mi < 4; mi++) {
#pragma unroll
        for (int nj = 0; nj < 4; nj++) {
            int row = row0 + wm * 64 + mi * 16 + r;
            int col = cb * 128 + wn * 32 + nj * 8 + c2 * 2;
            float b0 = 0.f, b1 = 0.f;
            if (GELU) { b0 = bias[col]; b1 = bias[col + 1]; }
            float x0 = acc[mi][nj][0] + b0;
            float x1 = acc[mi][nj][1] + b1;
            float x2 = acc[mi][nj][2] + b0;
            float x3 = acc[mi][nj][3] + b1;
            if constexpr (GELU) {
                x0 = gelu_exact(x0); x1 = gelu_exact(x1);
                x2 = gelu_exact(x2); x3 = gelu_exact(x3);
            }
            *(__half2*)&Ch[(size_t)row * ldc + col] =
                __float22half2_rn(make_float2(x0, x1));
            *(__half2*)&Ch[(size_t)(row + 8) * ldc + col] =
                __float22half2_rn(make_float2(x2, x3));
        }
    }
}

// ---------------------------------------------------------------------------
// Tail (R9/R13-proven): tmp transposed [dd][j], vectorized fp16 RP loads.
// ---------------------------------------------------------------------------
__global__ __launch_bounds__(256)
void tail_kernel(const __half* __restrict__ RP, const float* __restrict__ feats,
                 const float* __restrict__ basis, float* __restrict__ out)
{
    __shared__ __align__(16) float sT[16][3][52];
    __shared__ float sF[16][48];
    __shared__ float sBA[16][27];

    const int tid = threadIdx.x;
    const int el  = tid >> 4;
    const int o   = tid & 15;
    const size_t e = (size_t)blockIdx.x * 16 + el;

    const float* fe = feats + e * 48;
    sF[el][o*3+0] = fe[o*3+0];
    sF[el][o*3+1] = fe[o*3+1];
    sF[el][o*3+2] = fe[o*3+2];
    const float* be = basis + e * 27;
    for (int idx = o; idx < 27; idx += 16) sBA[el][idx] = be[idx];
    __syncthreads();

#pragma unroll
    for (int jj = 0; jj < 3; jj++) {
        int j = o + jj * 16;
        int i = j / 3, n = j - i * 3;
        float f0 = sF[el][i*3+0], f1 = sF[el][i*3+1], f2 = sF[el][i*3+2];
#pragma unroll
        for (int dd = 0; dd < 3; dd++) {
            sT[el][dd][j] = f0 * sBA[el][n*3 + dd]
                          + f1 * sBA[el][9 + n*3 + dd]
                          + f2 * sBA[el][18 + n*3 + dd];
        }
    }
    __syncthreads();

    const uint4* rp4 = (const uint4*)(RP + e * RPN + o * 48);
    const float* t0 = &sT[el][0][0];
    const float* t1 = &sT[el][1][0];
    const float* t2 = &sT[el][2][0];
    float s0 = 0.f, s1 = 0.f, s2 = 0.f;
#pragma unroll
    for (int q = 0; q < 6; q++) {
        uint4 u = rp4[q];
        const __half2* hp = (const __half2*)&u;
        float2 f01 = __half22float2(hp[0]);
        float2 f23 = __half22float2(hp[1]);
        float2 f45 = __half22float2(hp[2]);
        float2 f67 = __half22float2(hp[3]);
        float4 a0 = *(const float4*)&t0[q*8];
        float4 a1 = *(const float4*)&t0[q*8+4];
        s0 = fmaf(f01.x, a0.x, s0); s0 = fmaf(f01.y, a0.y, s0);
        s0 = fmaf(f23.x, a0.z, s0); s0 = fmaf(f23.y, a0.w, s0);
        s0 = fmaf(f45.x, a1.x, s0); s0 = fmaf(f45.y, a1.y, s0);
        s0 = fmaf(f67.x, a1.z, s0); s0 = fmaf(f67.y, a1.w, s0);
        float4 b0 = *(const float4*)&t1[q*8];
        float4 b1 = *(const float4*)&t1[q*8+4];
        s1 = fmaf(f01.x, b0.x, s1); s1 = fmaf(f01.y, b0.y, s1);
        s1 = fmaf(f23.x, b0.z, s1); s1 = fmaf(f23.y, b0.w, s1);
        s1 = fmaf(f45.x, b1.x, s1); s1 = fmaf(f45.y, b1.y, s1);
        s1 = fmaf(f67.x, b1.z, s1); s1 = fmaf(f67.y, b1.w, s1);
        float4 g0 = *(const float4*)&t2[q*8];
        float4 g1 = *(const float4*)&t2[q*8+4];
        s2 = fmaf(f01.x, g0.x, s2); s2 = fmaf(f01.y, g0.y, s2);
        s2 = fmaf(f23.x, g0.z, s2); s2 = fmaf(f23.y, g0.w, s2);
        s2 = fmaf(f45.x, g1.x, s2); s2 = fmaf(f45.y, g1.y, s2);
        s2 = fmaf(f67.x, g1.z, s2); s2 = fmaf(f67.y, g1.w, s2);
    }
    float* op = out + (e * 16 + o) * 3;
    op[0] = s0; op[1] = s1; op[2] = s2;
}

// ---------------------------------------------------------------------------
extern "C" void kernel_launch(void* const* d_in, const int* in_sizes, int n_in,
                              void* d_out, int out_size)
{
    const float* edges = (const float*)d_in[0];
    const float* feats = (const float*)d_in[1];
    const float* basis = (const float*)d_in[2];
    const float* W1    = (const float*)d_in[3];
    const float* b1    = (const float*)d_in[4];
    const float* W2    = (const float*)d_in[5];
    const float* b2    = (const float*)d_in[6];
    const float* W3    = (const float*)d_in[7];
    float* out = (float*)d_out;

    __half *W1h, *W1l, *W2h, *W3h, *H1, *H2, *RP;
    cudaGetSymbolAddress((void**)&W1h, g_W1h);
    cudaGetSymbolAddress((void**)&W1l, g_W1l);
    cudaGetSymbolAddress((void**)&W2h, g_W2h);
    cudaGetSymbolAddress((void**)&W3h, g_W3h);
    cudaGetSymbolAddress((void**)&H1,  g_H1);
    cudaGetSymbolAddress((void**)&H2,  g_H2);
    cudaGetSymbolAddress((void**)&RP,  g_RP);

    cudaFuncSetAttribute(hgemm1,
                         cudaFuncAttributeMaxDynamicSharedMemorySize, SM1);
    cudaFuncSetAttribute(hgemm<8, true>,
                         cudaFuncAttributeMaxDynamicSharedMemorySize, SMEM_SZ);
    cudaFuncSetAttribute(hgemm<8, false>,
                         cudaFuncAttributeMaxDynamicSharedMemorySize, SMEM_SZ);

    dim3 blk(256);
    // merged weight prep (one launch)
    prep_all<<<(8192 + 65536 + 196608) / 256, blk>>>(W1, W2, W3,
                                                     W1h, W1l, W2h, W3h);
    // layer 1: gelu(edges @ W1 + b1) -> H1 fp16 (multi-tile pipelined)
    hgemm1<<<dim3(E_TOTAL / 512, 2), blk, SM1>>>(edges, W1h, W1l, b1, H1);
    // layer 2: gelu(H1 @ W2 + b2) -> H2 fp16
    hgemm<8, true><<<dim3(E_TOTAL / 128, 2), blk, SMEM_SZ>>>(
        H1, 256, W2h, 256, b2, H2, 256);
    // layer 3: H2 @ W3[:,768:1536] -> RP fp16
    hgemm<8, false><<<dim3(E_TOTAL / 128, 6), blk, SMEM_SZ>>>(
        H2, 256, W3h, 256, nullptr, RP, RPN);
    // tail
    tail_kernel<<<E_TOTAL / 16, blk>>>(RP, feats, basis, out);
}

// round 16
// speedup vs baseline: 1.6177x; 1.0101x over previous
#include <cuda_runtime.h>
#include <cuda_fp16.h>
#include <math.h>
#include <stdint.h>

#define E_TOTAL 65536     // B*N*K
#define W3OFF   768       // SPLIT_OFF
#define RPN     768       // SPLIT_SZ

// ---- device scratch ----
__device__ __half g_W1h[256 * 32],  g_W1l[256 * 32];
__device__ __half g_W2h[256 * 256];
__device__ __half g_W3h[768 * 256];
__device__ __half g_H1[(size_t)E_TOTAL * 256];
__device__ __half g_H2[(size_t)E_TOTAL * 256];
__device__ __half g_RP[(size_t)E_TOTAL * RPN];   // fp16 RP (100 MB)

__device__ __forceinline__ float gelu_exact(float x) {
    return 0.5f * x * (1.0f + erff(x * 0.70710678118654752440f));
}

// ---------------------------------------------------------------------------
#define CPA16(dst_u32, src_ptr) \
    asm volatile("cp.async.cg.shared.global [%0], [%1], 16;" :: "r"(dst_u32), "l"(src_ptr))
#define CPA_COMMIT() asm volatile("cp.async.commit_group;" ::: "memory")
#define CPA_WAIT(n)  asm volatile("cp.async.wait_group %0;" :: "n"(n) : "memory")

#define LDSM4(R, addr)                                                        \
    asm volatile("ldmatrix.sync.aligned.m8n8.x4.shared.b16 {%0,%1,%2,%3}, [%4];" \
                 : "=r"((R)[0]), "=r"((R)[1]), "=r"((R)[2]), "=r"((R)[3])     \
                 : "r"(addr))

__device__ __forceinline__ void mma_f16(float* d, const uint32_t* a,
                                        uint32_t b0, uint32_t b1) {
    asm volatile(
        "mma.sync.aligned.m16n8k16.row.col.f32.f16.f16.f32 "
        "{%0,%1,%2,%3}, {%4,%5,%6,%7}, {%8,%9}, {%0,%1,%2,%3};"
        : "+f"(d[0]), "+f"(d[1]), "+f"(d[2]), "+f"(d[3])
        : "r"(a[0]), "r"(a[1]), "r"(a[2]), "r"(a[3]), "r"(b0), "r"(b1));
}

// 64B-row swizzle (GEMM1 path, validated R4/R6-R14)
__device__ __forceinline__ uint32_t soff(int r, int c) {
    return (uint32_t)((r * 4 + (c ^ ((r >> 1) & 3))) << 4);
}
// 128B-row swizzle (BK=64 stages): row r, 16B chunk c in 0..7
__device__ __forceinline__ uint32_t soff8(int r, int c) {
    return (uint32_t)(r * 128 + ((c ^ (r & 7)) << 4));
}

// ---------------------------------------------------------------------------
// merged weight prep: W1 (hi+lo, transposed), W2 (hi), W3 slice (hi)
// ---------------------------------------------------------------------------
__global__ void prep_all(const float* __restrict__ W1, const float* __restrict__ W2,
                         const float* __restrict__ W3,
                         __half* __restrict__ W1h, __half* __restrict__ W1l,
                         __half* __restrict__ W2h, __half* __restrict__ W3h)
{
    int idx = blockIdx.x * 256 + threadIdx.x;
    if (idx < 8192) {                          // W1: [256 n][32 k]
        int n = idx >> 5, k = idx & 31;
        float v = W1[k * 256 + n];
        __half h = __float2half_rn(v);
        W1h[idx] = h;
        W1l[idx] = __float2half_rn(v - __half2float(h));
    } else if (idx < 8192 + 65536) {           // W2: [256 n][256 k]
        int i = idx - 8192;
        int n = i >> 8, k = i & 255;
        W2h[i] = __float2half_rn(W2[k * 256 + n]);
    } else if (idx < 8192 + 65536 + 196608) {  // W3 slice: [768 n][256 k]
        int i = idx - 73728;
        int n = i >> 8, k = i & 255;
        W3h[i] = __float2half_rn(W3[(size_t)k * 1536 + W3OFF + n]);
    }
}

// ---------------------------------------------------------------------------
// GEMM1 multi-tile (R14-proven): grid (E/512, 2), 4 row-tiles/CTA,
// 2-deep cp.async pipeline on fp32 edges; W1 hi/lo loaded once.
// ---------------------------------------------------------------------------
#define SM1 57344

__global__ __launch_bounds__(256, 2)
void hgemm1(const float* __restrict__ edges,
            const __half* __restrict__ W1h, const __half* __restrict__ W1l,
            const float* __restrict__ b1, __half* __restrict__ H1)
{
    extern __shared__ __align__(128) char smem_c[];
    const uint32_t smem_u = (uint32_t)__cvta_generic_to_shared(smem_c);

    const int tid  = threadIdx.x;
    const int wid  = tid >> 5;
    const int lane = tid & 31;
    const int wm   = wid >> 2;
    const int wn   = wid & 3;
    const int cb   = blockIdx.y;
    const int tile0 = blockIdx.x * 4;

    const int lr0 = tid >> 2, lc0 = tid & 3;
    const int lr1 = (tid + 256) >> 2, lc1 = lc0;

    auto issue_edges = [&](int buf, int rt) {
        int row0 = (tile0 + rt) * 128;
#pragma unroll
        for (int i = 0; i < 4; i++) {
            int idx = tid + i * 256;
            int r = idx >> 3, c = idx & 7;
            CPA16(smem_u + buf * 16384 + (uint32_t)(r * 128 + (c ^ (r & 7)) * 16),
                  edges + (size_t)(row0 + r) * 32 + c * 4);
        }
    };
    auto issue_w1 = [&]() {
        CPA16(smem_u + 40960 + soff(lr0, lc0), W1h + (size_t)(cb * 128 + lr0) * 32 + lc0 * 8);
        CPA16(smem_u + 40960 + soff(lr1, lc1), W1h + (size_t)(cb * 128 + lr1) * 32 + lc1 * 8);
        CPA16(smem_u + 49152 + soff(lr0, lc0), W1l + (size_t)(cb * 128 + lr0) * 32 + lc0 * 8);
        CPA16(smem_u + 49152 + soff(lr1, lc1), W1l + (size_t)(cb * 128 + lr1) * 32 + lc1 * 8);
    };

    issue_edges(0, 0);
    issue_w1();
    CPA_COMMIT();
    issue_edges(1, 1);
    CPA_COMMIT();

    const int lr  = (lane & 7) | (((lane >> 3) & 1) << 3);
    const int lkc = lane >> 4;
    const int r4  = lane >> 2, c2 = lane & 3;
    const int cvr = tid >> 1, cvh = tid & 1;

#pragma unroll 1
    for (int rt = 0; rt < 4; rt++) {
        if (rt + 1 < 4) { CPA_WAIT(1); } else { CPA_WAIT(0); }
        __syncthreads();

        {
            const char* src = smem_c + (rt & 1) * 16384 + cvr * 128;
            __half2 hx[8];
#pragma unroll
            for (int q = 0; q < 4; q++) {
                int ch = cvh * 4 + q;
                float4 v = *(const float4*)(src + ((ch ^ (cvr & 7)) * 16));
                hx[2*q]   = __float22half2_rn(make_float2(v.x, v.y));
                hx[2*q+1] = __float22half2_rn(make_float2(v.z, v.w));
            }
            *(uint4*)(smem_c + 32768 + soff(cvr, cvh * 2))     = *(uint4*)&hx[0];
            *(uint4*)(smem_c + 32768 + soff(cvr, cvh * 2 + 1)) = *(uint4*)&hx[4];
        }
        __syncthreads();

        float acc[4][4][4];
#pragma unroll
        for (int i = 0; i < 4; i++)
#pragma unroll
            for (int j = 0; j < 4; j++)
#pragma unroll
                for (int q = 0; q < 4; q++) acc[i][j][q] = 0.f;

#pragma unroll
        for (int ks = 0; ks < 2; ks++) {
            const uint32_t xo = ks * 32;
            uint32_t ar[4][4];
#pragma unroll
            for (int mi = 0; mi < 4; mi++)
                LDSM4(ar[mi], (smem_u + 32768 + soff(wm * 64 + mi * 16 + lr, lkc)) ^ xo);
#pragma unroll
            for (int ng = 0; ng < 2; ng++) {
                uint32_t bh4[4], bl4[4];
                LDSM4(bh4, (smem_u + 40960 + soff(wn * 32 + ng * 16 + lr, lkc)) ^ xo);
                LDSM4(bl4, (smem_u + 49152 + soff(wn * 32 + ng * 16 + lr, lkc)) ^ xo);
#pragma unroll
                for (int mi = 0; mi < 4; mi++) {
                    mma_f16(acc[mi][ng*2],   ar[mi], bh4[0], bh4[2]);
                    mma_f16(acc[mi][ng*2+1], ar[mi], bh4[1], bh4[3]);
                    mma_f16(acc[mi][ng*2],   ar[mi], bl4[0], bl4[2]);
                    mma_f16(acc[mi][ng*2+1], ar[mi], bl4[1], bl4[3]);
                }
            }
        }

        int row0 = (tile0 + rt) * 128;
#pragma unroll
        for (int mi = 0; mi < 4; mi++) {
#pragma unroll
            for (int nj = 0; nj < 4; nj++) {
                int row = row0 + wm * 64 + mi * 16 + r4;
                int col = cb * 128 + wn * 32 + nj * 8 + c2 * 2;
                float bb0 = b1[col], bb1 = b1[col + 1];
                float x0 = gelu_exact(acc[mi][nj][0] + bb0);
                float x1 = gelu_exact(acc[mi][nj][1] + bb1);
                float x2 = gelu_exact(acc[mi][nj][2] + bb0);
                float x3 = gelu_exact(acc[mi][nj][3] + bb1);
                *(__half2*)&H1[(size_t)row * 256 + col] =
                    __float22half2_rn(make_float2(x0, x1));
                *(__half2*)&H1[(size_t)(row + 8) * 256 + col] =
                    __float22half2_rn(make_float2(x2, x3));
            }
        }

        if (rt + 2 < 4) {
            issue_edges(rt & 1, rt + 2);
            CPA_COMMIT();
        }
    }
}

// ---------------------------------------------------------------------------
// fp16 HMMA GEMM, BK=64 stages (half the pipeline barriers of the R8 kernel).
// BM=128 BN=128, 3-stage cp.async (32KB/stage), 8 warps (2m x 4n), warp 64x32.
// stage: A @0 (16K, 128 rows x 128B swizzled), B @16384 (16K).
// ---------------------------------------------------------------------------
#define STG64 32768
#define SMEM64 (3 * STG64)

template<int NT, bool GELU>
__global__ __launch_bounds__(256, 2)
void hgemm(const __half* __restrict__ Ain, int lda,
           const __half* __restrict__ Bh, int ldb,
           const float* __restrict__ bias,
           __half* __restrict__ Ch, int ldc)
{
    extern __shared__ __align__(128) char smem_c[];
    const uint32_t smem_u = (uint32_t)__cvta_generic_to_shared(smem_c);

    const int tid  = threadIdx.x;
    const int wid  = tid >> 5;
    const int lane = tid & 31;
    const int wm   = wid >> 2;
    const int wn   = wid & 3;
    const int row0 = blockIdx.x * 128;
    const int cb   = blockIdx.y;

    float acc[4][4][4];
#pragma unroll
    for (int i = 0; i < 4; i++)
#pragma unroll
        for (int j = 0; j < 4; j++)
#pragma unroll
            for (int q = 0; q < 4; q++) acc[i][j][q] = 0.f;

    // loader: 1024 16B chunks per 128x64 matrix, 4 per thread
    auto load_tile = [&](int s, int kt) {
        const uint32_t base = smem_u + s * STG64;
#pragma unroll
        for (int i = 0; i < 4; i++) {
            int idx = tid + i * 256;
            int r = idx >> 3, c = idx & 7;
            CPA16(base + soff8(r, c),
                  Ain + (size_t)(row0 + r) * lda + kt * 64 + c * 8);
            CPA16(base + 16384 + soff8(r, c),
                  Bh + (size_t)(cb * 128 + r) * ldb + kt * 64 + c * 8);
        }
    };

    load_tile(0, 0); CPA_COMMIT();
    if (NT > 1) { load_tile(1, 1); CPA_COMMIT(); }

    const int lr  = (lane & 7) | (((lane >> 3) & 1) << 3);
    const int lkc = lane >> 4;

#pragma unroll 1
    for (int kt = 0; kt < NT; kt++) {
        if (kt + 1 < NT) { CPA_WAIT(1); } else { CPA_WAIT(0); }
        __syncthreads();

        const uint32_t base = smem_u + (kt % 3) * STG64;
        // precompute ks=0 fragment addresses; ks selects chunk pair via ^(ks*32)
        uint32_t aA[4], bA[2];
#pragma unroll
        for (int mi = 0; mi < 4; mi++)
            aA[mi] = base + soff8(wm * 64 + mi * 16 + lr, lkc);
#pragma unroll
        for (int ng = 0; ng < 2; ng++)
            bA[ng] = base + 16384 + soff8(wn * 32 + ng * 16 + lr, lkc);

#pragma unroll
        for (int ks = 0; ks < 4; ks++) {
            const uint32_t xo = ks * 32;
            uint32_t ar[4][4];
#pragma unroll
            for (int mi = 0; mi < 4; mi++) LDSM4(ar[mi], aA[mi] ^ xo);
#pragma unroll
            for (int ng = 0; ng < 2; ng++) {
                uint32_t bh4[4];
                LDSM4(bh4, bA[ng] ^ xo);
#pragma unroll
                for (int mi = 0; mi < 4; mi++) {
                    mma_f16(acc[mi][ng*2],   ar[mi], bh4[0], bh4[2]);
                    mma_f16(acc[mi][ng*2+1], ar[mi], bh4[1], bh4[3]);
                }
            }
        }
        if (kt + 2 < NT) {
            load_tile((kt + 2) % 3, kt + 2);
            CPA_COMMIT();
        }
    }

    const int r = lane >> 2, c2 = lane & 3;
#pragma unroll
    for (int mi = 0; mi < 4; mi++) {
#pragma unroll
        for (int nj = 0; nj < 4; nj++) {
            int row = row0 + wm * 64 + mi * 16 + r;
            int col = cb * 128 + wn * 32 + nj * 8 + c2 * 2;
            float b0 = 0.f, b1 = 0.f;
            if (GELU) { b0 = bias[col]; b1 = bias[col + 1]; }
            float x0 = acc[mi][nj][0] + b0;
            float x1 = acc[mi][nj][1] + b1;
            float x2 = acc[mi][nj][2] + b0;
            float x3 = acc[mi][nj][3] + b1;
            if constexpr (GELU) {
                x0 = gelu_exact(x0); x1 = gelu_exact(x1);
                x2 = gelu_exact(x2); x3 = gelu_exact(x3);
            }
            *(__half2*)&Ch[(size_t)row * ldc + col] =
                __float22half2_rn(make_float2(x0, x1));
            *(__half2*)&Ch[(size_t)(row + 8) * ldc + col] =
                __float22half2_rn(make_float2(x2, x3));
        }
    }
}

// ---------------------------------------------------------------------------
// Tail (R9/R13-proven): tmp transposed [dd][j], vectorized fp16 RP loads.
// ---------------------------------------------------------------------------
__global__ __launch_bounds__(256)
void tail_kernel(const __half* __restrict__ RP, const float* __restrict__ feats,
                 const float* __restrict__ basis, float* __restrict__ out)
{
    __shared__ __align__(16) float sT[16][3][52];
    __shared__ float sF[16][48];
    __shared__ float sBA[16][27];

    const int tid = threadIdx.x;
    const int el  = tid >> 4;
    const int o   = tid & 15;
    const size_t e = (size_t)blockIdx.x * 16 + el;

    const float* fe = feats + e * 48;
    sF[el][o*3+0] = fe[o*3+0];
    sF[el][o*3+1] = fe[o*3+1];
    sF[el][o*3+2] = fe[o*3+2];
    const float* be = basis + e * 27;
    for (int idx = o; idx < 27; idx += 16) sBA[el][idx] = be[idx];
    __syncthreads();

#pragma unroll
    for (int jj = 0; jj < 3; jj++) {
        int j = o + jj * 16;
        int i = j / 3, n = j - i * 3;
        float f0 = sF[el][i*3+0], f1 = sF[el][i*3+1], f2 = sF[el][i*3+2];
#pragma unroll
        for (int dd = 0; dd < 3; dd++) {
            sT[el][dd][j] = f0 * sBA[el][n*3 + dd]
                          + f1 * sBA[el][9 + n*3 + dd]
                          + f2 * sBA[el][18 + n*3 + dd];
        }
    }
    __syncthreads();

    const uint4* rp4 = (const uint4*)(RP + e * RPN + o * 48);
    const float* t0 = &sT[el][0][0];
    const float* t1 = &sT[el][1][0];
    const float* t2 = &sT[el][2][0];
    float s0 = 0.f, s1 = 0.f, s2 = 0.f;
#pragma unroll
    for (int q = 0; q < 6; q++) {
        uint4 u = rp4[q];
        const __half2* hp = (const __half2*)&u;
        float2 f01 = __half22float2(hp[0]);
        float2 f23 = __half22float2(hp[1]);
        float2 f45 = __half22float2(hp[2]);
        float2 f67 = __half22float2(hp[3]);
        float4 a0 = *(const float4*)&t0[q*8];
        float4 a1 = *(const float4*)&t0[q*8+4];
        s0 = fmaf(f01.x, a0.x, s0); s0 = fmaf(f01.y, a0.y, s0);
        s0 = fmaf(f23.x, a0.z, s0); s0 = fmaf(f23.y, a0.w, s0);
        s0 = fmaf(f45.x, a1.x, s0); s0 = fmaf(f45.y, a1.y, s0);
        s0 = fmaf(f67.x, a1.z, s0); s0 = fmaf(f67.y, a1.w, s0);
        float4 b0 = *(const float4*)&t1[q*8];
        float4 b1 = *(const float4*)&t1[q*8+4];
        s1 = fmaf(f01.x, b0.x, s1); s1 = fmaf(f01.y, b0.y, s1);
        s1 = fmaf(f23.x, b0.z, s1); s1 = fmaf(f23.y, b0.w, s1);
        s1 = fmaf(f45.x, b1.x, s1); s1 = fmaf(f45.y, b1.y, s1);
        s1 = fmaf(f67.x, b1.z, s1); s1 = fmaf(f67.y, b1.w, s1);
        float4 g0 = *(const float4*)&t2[q*8];
        float4 g1 = *(const float4*)&t2[q*8+4];
        s2 = fmaf(f01.x, g0.x, s2); s2 = fmaf(f01.y, g0.y, s2);
        s2 = fmaf(f23.x, g0.z, s2); s2 = fmaf(f23.y, g0.w, s2);
        s2 = fmaf(f45.x, g1.x, s2); s2 = fmaf(f45.y, g1.y, s2);
        s2 = fmaf(f67.x, g1.z, s2); s2 = fmaf(f67.y, g1.w, s2);
    }
    float* op = out + (e * 16 + o) * 3;
    op[0] = s0; op[1] = s1; op[2] = s2;
}

// ---------------------------------------------------------------------------
extern "C" void kernel_launch(void* const* d_in, const int* in_sizes, int n_in,
                              void* d_out, int out_size)
{
    const float* edges = (const float*)d_in[0];
    const float* feats = (const float*)d_in[1];
    const float* basis = (const float*)d_in[2];
    const float* W1    = (const float*)d_in[3];
    const float* b1    = (const float*)d_in[4];
    const float* W2    = (const float*)d_in[5];
    const float* b2    = (const float*)d_in[6];
    const float* W3    = (const float*)d_in[7];
    float* out = (float*)d_out;

    __half *W1h, *W1l, *W2h, *W3h, *H1, *H2, *RP;
    cudaGetSymbolAddress((void**)&W1h, g_W1h);
    cudaGetSymbolAddress((void**)&W1l, g_W1l);
    cudaGetSymbolAddress((void**)&W2h, g_W2h);
    cudaGetSymbolAddress((void**)&W3h, g_W3h);
    cudaGetSymbolAddress((void**)&H1,  g_H1);
    cudaGetSymbolAddress((void**)&H2,  g_H2);
    cudaGetSymbolAddress((void**)&RP,  g_RP);

    cudaFuncSetAttribute(hgemm1,
                         cudaFuncAttributeMaxDynamicSharedMemorySize, SM1);
    cudaFuncSetAttribute(hgemm<4, true>,
                         cudaFuncAttributeMaxDynamicSharedMemorySize, SMEM64);
    cudaFuncSetAttribute(hgemm<4, false>,
                         cudaFuncAttributeMaxDynamicSharedMemorySize, SMEM64);

    dim3 blk(256);
    // merged weight prep
    prep_all<<<(8192 + 65536 + 196608) / 256, blk>>>(W1, W2, W3,
                                                     W1h, W1l, W2h, W3h);
    // layer 1: gelu(edges @ W1 + b1) -> H1 fp16 (multi-tile pipelined)
    hgemm1<<<dim3(E_TOTAL / 512, 2), blk, SM1>>>(edges, W1h, W1l, b1, H1);
    // layer 2: gelu(H1 @ W2 + b2) -> H2 fp16  (BK=64 stages)
    hgemm<4, true><<<dim3(E_TOTAL / 128, 2), blk, SMEM64>>>(
        H1, 256, W2h, 256, b2, H2, 256);
    // layer 3: H2 @ W3[:,768:1536] -> RP fp16  (BK=64 stages)
    hgemm<4, false><<<dim3(E_TOTAL / 128, 6), blk, SMEM64>>>(
        H2, 256, W3h, 256, nullptr, RP, RPN);
    // tail
    tail_kernel<<<E_TOTAL / 16, blk>>>(RP, feats, basis, out);
}